// round 12
// baseline (speedup 1.0000x reference)
#include <cuda_runtime.h>
#include <math_constants.h>
#include <math.h>

#define B_      8
#define C_      32
#define K_      5
#define HW_     65536
#define TILES_  32
#define TPX_    2048
#define SST_    (4*1024 + 32*5 + 32 + 5 + 27)   // 4 ZZ team slices + GZ + S + Gs
#define ZZOFF_  0
#define GZOFF_  4096
#define SOFF_   (4096 + 160)
#define GSOFF_  (4096 + 192)
#define CHUNKS_ 256
#define EPS_    1e-6f
#define CLOG2PI_ (32.0f * 1.8378770664093453f)

typedef unsigned long long u64;

// ---- scratch (static device globals; no allocation) ----
__device__ float g_part1[B_ * TILES_ * SST_];
__device__ float g_P[B_ * K_ * C_ * C_];     // packed upper-tri P, diag halved, lower zero
__device__ float g_Hb[B_ * K_ * C_];         // -q = -(P mu)
__device__ float g_Ck[B_ * K_];              // phi - 0.5*(c*log2pi + logdet + r)
__device__ float g_part2[B_ * K_ * CHUNKS_ * 2];

// ---- packed f32x2 helpers (sm_103a FFMA2 path, PTX-only) ----
__device__ __forceinline__ u64 fma2(u64 a, u64 b, u64 c) {
    u64 d;
    asm("fma.rn.f32x2 %0, %1, %2, %3;" : "=l"(d) : "l"(a), "l"(b), "l"(c));
    return d;
}
__device__ __forceinline__ u64 pack2(float lo, float hi) {
    u64 d;
    asm("mov.b64 %0, {%1, %2};" : "=l"(d) : "f"(lo), "f"(hi));
    return d;
}
__device__ __forceinline__ void unpack2(u64 v, float& lo, float& hi) {
    asm("mov.b64 {%0, %1}, %2;" : "=f"(lo), "=f"(hi) : "l"(v));
}

// =====================================================================
// Kernel 1: per-(b,tile) partial sufficient statistics (R8-proven).
// =====================================================================
__global__ __launch_bounds__(256, 2) void k_stats(const float* __restrict__ z,
                                                  const float* __restrict__ g)
{
    const int tile = blockIdx.x, b = blockIdx.y;
    const int tid = threadIdx.x, w = tid >> 5, l = tid & 31;
    __shared__ float zs[256][36];   // pixel-major, float4-aligned rows
    __shared__ float gs[256][8];

    const float* zb = z + (size_t)b * C_ * HW_;
    const float* gb = g + (size_t)b * K_ * HW_;
    const int base0 = tile * TPX_;

    const int team = tid >> 6;
    const int thr  = tid & 63;
    const int ti   = thr >> 3, tj = thr & 7;

    float acc[4][4];
    #pragma unroll
    for (int u = 0; u < 4; ++u)
        #pragma unroll
        for (int v = 0; v < 4; ++v) acc[u][v] = 0.f;
    float bg0 = 0.f, bg1 = 0.f, bg2 = 0.f, bg3 = 0.f, bg4 = 0.f;
    float bs = 0.f;
    float bgs0 = 0.f, bgs1 = 0.f, bgs2 = 0.f, bgs3 = 0.f, bgs4 = 0.f;

    #pragma unroll 1
    for (int ch = 0; ch < 8; ++ch) {
        const int base = base0 + (ch << 8) + tid;
        __syncthreads();
        #pragma unroll
        for (int c4 = 0; c4 < 8; ++c4) {
            float4 v;
            v.x = zb[(size_t)(4 * c4 + 0) * HW_ + base];
            v.y = zb[(size_t)(4 * c4 + 1) * HW_ + base];
            v.z = zb[(size_t)(4 * c4 + 2) * HW_ + base];
            v.w = zb[(size_t)(4 * c4 + 3) * HW_ + base];
            *reinterpret_cast<float4*>(&zs[tid][4 * c4]) = v;
        }
        {
            float4 gv;
            gv.x = gb[(size_t)0 * HW_ + base];
            gv.y = gb[(size_t)1 * HW_ + base];
            gv.z = gb[(size_t)2 * HW_ + base];
            gv.w = gb[(size_t)3 * HW_ + base];
            *reinterpret_cast<float4*>(&gs[tid][0]) = gv;
            gs[tid][4] = gb[(size_t)4 * HW_ + base];
        }
        __syncthreads();

        // phase A: SYRK over this team's 64 pixels
        const int x0 = team << 6;
        #pragma unroll 2
        for (int x = x0; x < x0 + 64; ++x) {
            const float4 a  = *reinterpret_cast<const float4*>(&zs[x][4 * ti]);
            const float4 bb = *reinterpret_cast<const float4*>(&zs[x][4 * tj]);
            acc[0][0] = fmaf(a.x, bb.x, acc[0][0]);
            acc[0][1] = fmaf(a.x, bb.y, acc[0][1]);
            acc[0][2] = fmaf(a.x, bb.z, acc[0][2]);
            acc[0][3] = fmaf(a.x, bb.w, acc[0][3]);
            acc[1][0] = fmaf(a.y, bb.x, acc[1][0]);
            acc[1][1] = fmaf(a.y, bb.y, acc[1][1]);
            acc[1][2] = fmaf(a.y, bb.z, acc[1][2]);
            acc[1][3] = fmaf(a.y, bb.w, acc[1][3]);
            acc[2][0] = fmaf(a.z, bb.x, acc[2][0]);
            acc[2][1] = fmaf(a.z, bb.y, acc[2][1]);
            acc[2][2] = fmaf(a.z, bb.z, acc[2][2]);
            acc[2][3] = fmaf(a.z, bb.w, acc[2][3]);
            acc[3][0] = fmaf(a.w, bb.x, acc[3][0]);
            acc[3][1] = fmaf(a.w, bb.y, acc[3][1]);
            acc[3][2] = fmaf(a.w, bb.z, acc[3][2]);
            acc[3][3] = fmaf(a.w, bb.w, acc[3][3]);
        }

        // phase B: this warp's 32 pixels, all 5 g rows
        const int xb = w << 5;
        #pragma unroll 4
        for (int xx = 0; xx < 32; ++xx) {
            const int x = xb + xx;
            const float zv = zs[x][l];
            const float4 g4 = *reinterpret_cast<const float4*>(&gs[x][0]);
            const float g5 = gs[x][4];
            bg0 = fmaf(g4.x, zv, bg0);
            bg1 = fmaf(g4.y, zv, bg1);
            bg2 = fmaf(g4.z, zv, bg2);
            bg3 = fmaf(g4.w, zv, bg3);
            bg4 = fmaf(g5,   zv, bg4);
            bs += zv;
            bgs0 += g4.x; bgs1 += g4.y; bgs2 += g4.z; bgs3 += g4.w; bgs4 += g5;
        }
    }

    float* p = g_part1 + (size_t)(b * TILES_ + tile) * SST_;
    #pragma unroll
    for (int u = 0; u < 4; ++u)
        #pragma unroll
        for (int v = 0; v < 4; ++v)
            p[ZZOFF_ + team * 1024 + (4 * ti + u) * 32 + (4 * tj + v)] = acc[u][v];

    // cross-warp reduce GZ/S/Gs (alias scratch into gs; it is dead now)
    __syncthreads();
    float* red = &gs[0][0];
    red[(w * 5 + 0) * 32 + l] = bg0;
    red[(w * 5 + 1) * 32 + l] = bg1;
    red[(w * 5 + 2) * 32 + l] = bg2;
    red[(w * 5 + 3) * 32 + l] = bg3;
    red[(w * 5 + 4) * 32 + l] = bg4;
    red[1280 + w * 32 + l] = bs;
    if (l == 0) {
        red[1536 + w * 5 + 0] = bgs0;
        red[1536 + w * 5 + 1] = bgs1;
        red[1536 + w * 5 + 2] = bgs2;
        red[1536 + w * 5 + 3] = bgs3;
        red[1536 + w * 5 + 4] = bgs4;
    }
    __syncthreads();
    if (w < 5) {
        float a = 0.f;
        #pragma unroll
        for (int w2 = 0; w2 < 8; ++w2) a += red[(w2 * 5 + w) * 32 + l];
        p[GZOFF_ + w * 32 + l] = a;
    } else if (w == 5) {
        float a = 0.f;
        #pragma unroll
        for (int w2 = 0; w2 < 8; ++w2) a += red[1280 + w2 * 32 + l];
        p[SOFF_ + l] = a;
    } else if (w == 6 && l < 5) {
        float a = 0.f;
        #pragma unroll
        for (int w2 = 0; w2 < 8; ++w2) a += red[1536 + w2 * 5 + l];
        p[GSOFF_ + l] = a;
    }
}

__device__ __forceinline__ float wsum(float v)
{
    #pragma unroll
    for (int o = 16; o; o >>= 1) v += __shfl_xor_sync(0xffffffffu, v, o);
    return v;
}

// =====================================================================
// Kernel 2 (R8-proven): per-(b,k) block of 256 threads reduces tile
// partials; warp 0 does mu, cov, Cholesky, P = L^-T L^-1, q, r, logdet.
// =====================================================================
__global__ __launch_bounds__(256) void k_prep()
{
    const int bk = blockIdx.x;
    const int b = bk / K_, k = bk % K_;
    const int tid = threadIdx.x, l = tid & 31;
    __shared__ float st[1090];          // ZZ(1024) GZ_k(32) S(32) Gs_k(1)
    __shared__ float A [32][33];
    __shared__ float Ai[32][33];
    __shared__ float Pm[32][33];
    __shared__ float mu[32], Sv[32];

    const float* p1 = g_part1 + (size_t)b * TILES_ * SST_;

    // ZZ: sum 32 tiles x 4 team slices
    for (int s = tid; s < 1024; s += 256) {
        float acc = 0.f;
        for (int t = 0; t < TILES_; ++t) {
            const float* pp = p1 + (size_t)t * SST_;
            acc += pp[s] + pp[1024 + s] + pp[2048 + s] + pp[3072 + s];
        }
        st[s] = acc;
    }
    // GZ row k, S, Gs_k
    if (tid < 32) {
        float a1 = 0.f, a2 = 0.f, a3 = 0.f;
        for (int t = 0; t < TILES_; ++t) {
            const float* pp = p1 + (size_t)t * SST_;
            a1 += pp[GZOFF_ + k * 32 + tid];
            a2 += pp[SOFF_ + tid];
            if (tid == 0) a3 += pp[GSOFF_ + k];
        }
        st[1024 + tid] = a1;
        st[1056 + tid] = a2;
        if (tid == 0) st[1088] = a3;
    }
    __syncthreads();
    if (tid >= 32) return;

    const float Gs = st[1088];

    // mu = GZ/(Gs+eps), then L2-normalize over channels
    float m = st[1024 + l] / (Gs + EPS_);
    float nrm = sqrtf(wsum(m * m));
    m = m / (EPS_ + nrm);
    mu[l] = m; Sv[l] = st[1056 + l];
    __syncwarp();

    // cov = ZZ - mu S^T - S mu^T + hw mu mu^T
    #pragma unroll 1
    for (int i = 0; i < 32; ++i)
        A[i][l] = st[i * 32 + l] - mu[i] * Sv[l] - m * Sv[i] + 65536.0f * mu[i] * m;
    __syncwarp();

    // diag += max(diag, eps)
    {
        float dg = A[l][l];
        A[l][l] = dg + fmaxf(dg, EPS_);
    }
    __syncwarp();

    // Frobenius normalize
    float sq = 0.f;
    for (int i = 0; i < 32; ++i) sq += A[i][l] * A[i][l];
    float fro = sqrtf(wsum(sq));
    float sc = 1.0f / (EPS_ + fro);
    for (int i = 0; i < 32; ++i) A[i][l] *= sc;
    __syncwarp();

    // Cholesky (lower, in place)
    for (int j = 0; j < 32; ++j) {
        if (l == 0) A[j][j] = sqrtf(A[j][j]);
        __syncwarp();
        float inv = 1.0f / A[j][j];
        if (l > j) A[l][j] *= inv;
        __syncwarp();
        for (int m2 = j + 1; m2 < 32; ++m2) {
            float lmj = A[m2][j];
            if (l >= m2) A[l][m2] = fmaf(-A[l][j], lmj, A[l][m2]);
        }
        __syncwarp();
    }
    float logdet2 = 2.0f * wsum(logf(A[l][l]));

    // Ai = L^-1 (lower); lane l owns column l
    for (int i = 0; i < 32; ++i) Ai[i][l] = 0.0f;
    __syncwarp();
    Ai[l][l] = 1.0f / A[l][l];
    for (int i = l + 1; i < 32; ++i) {
        float s = 0.f;
        for (int m2 = l; m2 < i; ++m2) s = fmaf(A[i][m2], Ai[m2][l], s);
        Ai[i][l] = -s / A[i][i];
    }
    __syncwarp();

    // P = Ai^T Ai
    for (int i = 0; i < 32; ++i) {
        float s = 0.f;
        for (int m2 = 0; m2 < 32; ++m2) s = fmaf(Ai[m2][i], Ai[m2][l], s);
        Pm[i][l] = s;
    }
    __syncwarp();

    // q = P mu, r = mu^T P mu
    float q = 0.f;
    for (int j = 0; j < 32; ++j) q = fmaf(Pm[l][j], mu[j], q);
    float r = wsum(mu[l] * q);

    // pack: upper triangle, halved diagonal, zero below
    float* Pd = g_P + (size_t)bk * (C_ * C_);
    for (int i = 0; i < 32; ++i) {
        float v = (l < i) ? 0.0f : ((l == i) ? 0.5f * Pm[i][i] : Pm[i][l]);
        Pd[i * 32 + l] = v;
    }
    g_Hb[bk * C_ + l] = -q;
    if (l == 0) {
        float phi = Gs / 65536.0f;
        g_Ck[bk] = phi - 0.5f * (CLOG2PI_ + logdet2 + r);
    }
}

// =====================================================================
// Kernel 3: packed-f32x2 quadratic form, CHANNEL-pair packing,
// ONE pixel per thread: z state halves to 32 regs -> 3 blocks/SM
// (24 warps) for latency hiding. P broadcast loads (LDS.128) ride the
// MIO pipe and overlap the fma pipe. 2048 blocks of 256 threads.
// =====================================================================
__global__ __launch_bounds__(256, 3) void k_maha(const float* __restrict__ z)
{
    const int chunk = blockIdx.x;
    const int b     = blockIdx.y;
    const int tid   = threadIdx.x;
    const int wid   = tid >> 5, lid = tid & 31;

    __shared__ __align__(16) float Ps[K_ * 1024];   // 20KB plain P rows
    __shared__ __align__(16) float H2[K_ * 64];     // (H_{2i},0,H_{2i+1},0) x16 per k
    __shared__ float rmx[8 * K_], rsm[8 * K_];

    const float4* Pb4 = reinterpret_cast<const float4*>(g_P + (size_t)b * K_ * 1024);
    float4* Ps4 = reinterpret_cast<float4*>(Ps);
    #pragma unroll
    for (int r = 0; r < K_; ++r) Ps4[tid + r * 256] = Pb4[tid + r * 256];
    if (tid < K_ * 16) {
        const int k = tid / 16, i = tid % 16;
        const float* Hk = g_Hb + (b * K_ + k) * 32;
        float4 h;
        h.x = Hk[2 * i]; h.y = 0.f; h.z = Hk[2 * i + 1]; h.w = 0.f;
        *reinterpret_cast<float4*>(&H2[k * 64 + 4 * i]) = h;
    }
    __syncthreads();

    const float* zb = z + (size_t)b * C_ * HW_;
    const int n = chunk * 256 + tid;

    // zA[i] = (z_{2i}, z_{2i+1}) of THIS thread's pixel (channel pairs)
    u64 zA[16];
    #pragma unroll 4
    for (int i = 0; i < 16; ++i) {
        const float a0 = zb[(size_t)(2 * i)     * HW_ + n];
        const float a1 = zb[(size_t)(2 * i + 1) * HW_ + n];
        zA[i] = pack2(a0, a1);
    }

    float vk[K_];

    #pragma unroll 1
    for (int k = 0; k < K_; ++k) {
        const float* Pk = &Ps[k * 1024];
        const u64* H2k = reinterpret_cast<const u64*>(&H2[k * 64]);
        u64 s0 = 0ull;
        #pragma unroll
        for (int i = 0; i < 16; ++i) {
            const int c0 = 2 * i, c1 = c0 + 1;
            const int jj0 = i & ~1;
            u64 ta = H2k[2 * i];       // (H_c0, 0)
            u64 tb = H2k[2 * i + 1];   // (H_c1, 0)
            const u64* rowA = reinterpret_cast<const u64*>(Pk + c0 * 32);
            const u64* rowB = reinterpret_cast<const u64*>(Pk + c1 * 32);
            #pragma unroll
            for (int jj = jj0; jj < 16; jj += 2) {
                const ulonglong2 pa = *reinterpret_cast<const ulonglong2*>(rowA + jj);
                const ulonglong2 pb = *reinterpret_cast<const ulonglong2*>(rowB + jj);
                ta = fma2(pa.x, zA[jj],     ta);
                tb = fma2(pb.x, zA[jj],     tb);
                ta = fma2(pa.y, zA[jj + 1], ta);
                tb = fma2(pb.y, zA[jj + 1], tb);
            }
            float x0, x1, y0, y1;
            unpack2(ta, x0, x1);
            unpack2(tb, y0, y1);
            const u64 T0 = pack2(x0 + x1, y0 + y1);   // (t_c0, t_c1)
            s0 = fma2(zA[i], T0, s0);
        }
        float e0, e1;
        unpack2(s0, e0, e1);
        vk[k] = -(e0 + e1);
    }

    // warp reduce: per-thread (m=v, s=1) logsumexp-merge, then cross-warp
    #pragma unroll
    for (int k = 0; k < K_; ++k) {
        float m = vk[k], s = 1.0f;
        #pragma unroll
        for (int o = 16; o; o >>= 1) {
            float m2 = __shfl_xor_sync(0xffffffffu, m, o);
            float s2 = __shfl_xor_sync(0xffffffffu, s, o);
            float nm = fmaxf(m, m2);
            s = s * __expf(m - nm) + s2 * __expf(m2 - nm);
            m = nm;
        }
        if (lid == 0) { rmx[wid * K_ + k] = m; rsm[wid * K_ + k] = s; }
    }
    __syncthreads();
    if (tid < K_) {
        float m = rmx[tid], s = rsm[tid];
        #pragma unroll
        for (int w2 = 1; w2 < 8; ++w2) {
            float m2 = rmx[w2 * K_ + tid], s2 = rsm[w2 * K_ + tid];
            float nm = fmaxf(m, m2);
            s = s * __expf(m - nm) + s2 * __expf(m2 - nm);
            m = nm;
        }
        float* o = g_part2 + (size_t)((b * K_ + tid) * CHUNKS_ + chunk) * 2;
        o[0] = m; o[1] = s;
    }
}

// =====================================================================
// Kernel 4 (R8-proven): combine chunk partials -> energy scalar.
// =====================================================================
__global__ __launch_bounds__(1024) void k_final(float* __restrict__ out)
{
    __shared__ float vals[B_ * K_];
    const int tid = threadIdx.x, w = tid >> 5, lid = tid & 31;

    for (int bk = w; bk < B_ * K_; bk += 32) {
        float m = -CUDART_INF_F, s = 0.0f;
        for (int c = lid; c < CHUNKS_; c += 32) {
            const float* o = g_part2 + (size_t)(bk * CHUNKS_ + c) * 2;
            const float m2 = o[0], s2 = o[1];
            const float nm = fmaxf(m, m2);
            s = s * __expf(m - nm) + s2 * __expf(m2 - nm);
            m = nm;
        }
        #pragma unroll
        for (int o = 16; o; o >>= 1) {
            const float m2 = __shfl_xor_sync(0xffffffffu, m, o);
            const float s2 = __shfl_xor_sync(0xffffffffu, s, o);
            const float nm = fmaxf(m, m2);
            s = s * __expf(m - nm) + s2 * __expf(m2 - nm);
            m = nm;
        }
        if (lid == 0) vals[bk] = g_Ck[bk] + m + logf(s);
    }
    __syncthreads();
    if (tid == 0) {
        float acc = 0.f;
        #pragma unroll
        for (int t = 0; t < B_ * K_; ++t) acc += vals[t];
        out[0] = -(acc / 40.0f) / 65536.0f;
    }
}

// =====================================================================
extern "C" void kernel_launch(void* const* d_in, const int* in_sizes, int n_in,
                              void* d_out, int out_size)
{
    (void)in_sizes; (void)n_in; (void)out_size;
    const float* z = (const float*)d_in[0];
    const float* g = (const float*)d_in[1];

    k_stats <<<dim3(TILES_, B_), 256>>>(z, g);
    k_prep  <<<B_ * K_, 256>>>();
    k_maha  <<<dim3(CHUNKS_, B_), 256>>>(z);
    k_final <<<1, 1024>>>((float*)d_out);
}

// round 13
// speedup vs baseline: 1.1501x; 1.1501x over previous
#include <cuda_runtime.h>
#include <math_constants.h>
#include <math.h>

#define B_      8
#define C_      32
#define K_      5
#define HW_     65536
#define TILES_  32
#define TPX_    2048
#define SST_    (4*1024 + 32*5 + 32 + 5 + 27)   // 4 ZZ team slices + GZ + S + Gs
#define ZZOFF_  0
#define GZOFF_  4096
#define SOFF_   (4096 + 160)
#define GSOFF_  (4096 + 192)
#define CHUNKS_ 128
#define EPS_    1e-6f
#define CLOG2PI_ (32.0f * 1.8378770664093453f)

typedef unsigned long long u64;

// ---- scratch (static device globals; no allocation) ----
__device__ float g_part1[B_ * TILES_ * SST_];
__device__ float g_P[B_ * K_ * C_ * C_];     // packed upper-tri P, diag halved, lower zero
__device__ float g_Hb[B_ * K_ * C_];         // -q = -(P mu)
__device__ float g_Ck[B_ * K_];              // phi - 0.5*(c*log2pi + logdet + r)
__device__ float g_part2[B_ * K_ * CHUNKS_ * 2];

// ---- packed f32x2 helpers (sm_103a FFMA2 path, PTX-only) ----
__device__ __forceinline__ u64 fma2(u64 a, u64 b, u64 c) {
    u64 d;
    asm("fma.rn.f32x2 %0, %1, %2, %3;" : "=l"(d) : "l"(a), "l"(b), "l"(c));
    return d;
}
__device__ __forceinline__ u64 pack2(float lo, float hi) {
    u64 d;
    asm("mov.b64 %0, {%1, %2};" : "=l"(d) : "f"(lo), "f"(hi));
    return d;
}
__device__ __forceinline__ void unpack2(u64 v, float& lo, float& hi) {
    asm("mov.b64 {%0, %1}, %2;" : "=f"(lo), "=f"(hi) : "l"(v));
}

// =====================================================================
// Kernel 1: per-(b,tile) partial sufficient statistics.
// R8 structure + SOFTWARE PIPELINE: chunk ch+1's 37 LDGs are issued
// BEFORE computing chunk ch, so the ~600-cycle global latency hides
// under ~3500 cycles of SYRK FMA instead of serializing with it.
// =====================================================================
__global__ __launch_bounds__(256, 2) void k_stats(const float* __restrict__ z,
                                                  const float* __restrict__ g)
{
    const int tile = blockIdx.x, b = blockIdx.y;
    const int tid = threadIdx.x, w = tid >> 5, l = tid & 31;
    __shared__ float zs[256][36];   // pixel-major, float4-aligned rows
    __shared__ float gs[256][8];

    const float* zb = z + (size_t)b * C_ * HW_;
    const float* gb = g + (size_t)b * K_ * HW_;
    const int base0 = tile * TPX_;

    const int team = tid >> 6;
    const int thr  = tid & 63;
    const int ti   = thr >> 3, tj = thr & 7;

    float acc[4][4];
    #pragma unroll
    for (int u = 0; u < 4; ++u)
        #pragma unroll
        for (int v = 0; v < 4; ++v) acc[u][v] = 0.f;
    float bg0 = 0.f, bg1 = 0.f, bg2 = 0.f, bg3 = 0.f, bg4 = 0.f;
    float bs = 0.f;
    float bgs0 = 0.f, bgs1 = 0.f, bgs2 = 0.f, bgs3 = 0.f, bgs4 = 0.f;

    // prefetch registers for the NEXT chunk
    float pz[32], pg[5];
    {
        const int base = base0 + tid;
        #pragma unroll
        for (int c = 0; c < 32; ++c) pz[c] = zb[(size_t)c * HW_ + base];
        #pragma unroll
        for (int r = 0; r < 5; ++r) pg[r] = gb[(size_t)r * HW_ + base];
    }

    #pragma unroll 1
    for (int ch = 0; ch < 8; ++ch) {
        // store prefetched chunk ch to smem
        #pragma unroll
        for (int c4 = 0; c4 < 8; ++c4) {
            float4 v;
            v.x = pz[4 * c4 + 0];
            v.y = pz[4 * c4 + 1];
            v.z = pz[4 * c4 + 2];
            v.w = pz[4 * c4 + 3];
            *reinterpret_cast<float4*>(&zs[tid][4 * c4]) = v;
        }
        {
            float4 gv;
            gv.x = pg[0]; gv.y = pg[1]; gv.z = pg[2]; gv.w = pg[3];
            *reinterpret_cast<float4*>(&gs[tid][0]) = gv;
            gs[tid][4] = pg[4];
        }
        __syncthreads();

        // issue LDGs for chunk ch+1 NOW; compute below hides the latency
        if (ch < 7) {
            const int base = base0 + ((ch + 1) << 8) + tid;
            #pragma unroll
            for (int c = 0; c < 32; ++c) pz[c] = zb[(size_t)c * HW_ + base];
            #pragma unroll
            for (int r = 0; r < 5; ++r) pg[r] = gb[(size_t)r * HW_ + base];
        }

        // phase A: SYRK over this team's 64 pixels
        const int x0 = team << 6;
        #pragma unroll 2
        for (int x = x0; x < x0 + 64; ++x) {
            const float4 a  = *reinterpret_cast<const float4*>(&zs[x][4 * ti]);
            const float4 bb = *reinterpret_cast<const float4*>(&zs[x][4 * tj]);
            acc[0][0] = fmaf(a.x, bb.x, acc[0][0]);
            acc[0][1] = fmaf(a.x, bb.y, acc[0][1]);
            acc[0][2] = fmaf(a.x, bb.z, acc[0][2]);
            acc[0][3] = fmaf(a.x, bb.w, acc[0][3]);
            acc[1][0] = fmaf(a.y, bb.x, acc[1][0]);
            acc[1][1] = fmaf(a.y, bb.y, acc[1][1]);
            acc[1][2] = fmaf(a.y, bb.z, acc[1][2]);
            acc[1][3] = fmaf(a.y, bb.w, acc[1][3]);
            acc[2][0] = fmaf(a.z, bb.x, acc[2][0]);
            acc[2][1] = fmaf(a.z, bb.y, acc[2][1]);
            acc[2][2] = fmaf(a.z, bb.z, acc[2][2]);
            acc[2][3] = fmaf(a.z, bb.w, acc[2][3]);
            acc[3][0] = fmaf(a.w, bb.x, acc[3][0]);
            acc[3][1] = fmaf(a.w, bb.y, acc[3][1]);
            acc[3][2] = fmaf(a.w, bb.z, acc[3][2]);
            acc[3][3] = fmaf(a.w, bb.w, acc[3][3]);
        }

        // phase B: this warp's 32 pixels, all 5 g rows
        const int xb = w << 5;
        #pragma unroll 4
        for (int xx = 0; xx < 32; ++xx) {
            const int x = xb + xx;
            const float zv = zs[x][l];
            const float4 g4 = *reinterpret_cast<const float4*>(&gs[x][0]);
            const float g5 = gs[x][4];
            bg0 = fmaf(g4.x, zv, bg0);
            bg1 = fmaf(g4.y, zv, bg1);
            bg2 = fmaf(g4.z, zv, bg2);
            bg3 = fmaf(g4.w, zv, bg3);
            bg4 = fmaf(g5,   zv, bg4);
            bs += zv;
            bgs0 += g4.x; bgs1 += g4.y; bgs2 += g4.z; bgs3 += g4.w; bgs4 += g5;
        }
        __syncthreads();   // all reads done before next iteration's STS
    }

    float* p = g_part1 + (size_t)(b * TILES_ + tile) * SST_;
    #pragma unroll
    for (int u = 0; u < 4; ++u)
        #pragma unroll
        for (int v = 0; v < 4; ++v)
            p[ZZOFF_ + team * 1024 + (4 * ti + u) * 32 + (4 * tj + v)] = acc[u][v];

    // cross-warp reduce GZ/S/Gs (alias scratch into gs; it is dead now)
    float* red = &gs[0][0];
    red[(w * 5 + 0) * 32 + l] = bg0;
    red[(w * 5 + 1) * 32 + l] = bg1;
    red[(w * 5 + 2) * 32 + l] = bg2;
    red[(w * 5 + 3) * 32 + l] = bg3;
    red[(w * 5 + 4) * 32 + l] = bg4;
    red[1280 + w * 32 + l] = bs;
    if (l == 0) {
        red[1536 + w * 5 + 0] = bgs0;
        red[1536 + w * 5 + 1] = bgs1;
        red[1536 + w * 5 + 2] = bgs2;
        red[1536 + w * 5 + 3] = bgs3;
        red[1536 + w * 5 + 4] = bgs4;
    }
    __syncthreads();
    if (w < 5) {
        float a = 0.f;
        #pragma unroll
        for (int w2 = 0; w2 < 8; ++w2) a += red[(w2 * 5 + w) * 32 + l];
        p[GZOFF_ + w * 32 + l] = a;
    } else if (w == 5) {
        float a = 0.f;
        #pragma unroll
        for (int w2 = 0; w2 < 8; ++w2) a += red[1280 + w2 * 32 + l];
        p[SOFF_ + l] = a;
    } else if (w == 6 && l < 5) {
        float a = 0.f;
        #pragma unroll
        for (int w2 = 0; w2 < 8; ++w2) a += red[1536 + w2 * 5 + l];
        p[GSOFF_ + l] = a;
    }
}

__device__ __forceinline__ float wsum(float v)
{
    #pragma unroll
    for (int o = 16; o; o >>= 1) v += __shfl_xor_sync(0xffffffffu, v, o);
    return v;
}

// =====================================================================
// Kernel 2 (R8-proven): per-(b,k) block of 256 threads reduces tile
// partials; warp 0 does mu, cov, Cholesky, P = L^-T L^-1, q, r, logdet.
// =====================================================================
__global__ __launch_bounds__(256) void k_prep()
{
    const int bk = blockIdx.x;
    const int b = bk / K_, k = bk % K_;
    const int tid = threadIdx.x, l = tid & 31;
    __shared__ float st[1090];          // ZZ(1024) GZ_k(32) S(32) Gs_k(1)
    __shared__ float A [32][33];
    __shared__ float Ai[32][33];
    __shared__ float Pm[32][33];
    __shared__ float mu[32], Sv[32];

    const float* p1 = g_part1 + (size_t)b * TILES_ * SST_;

    // ZZ: sum 32 tiles x 4 team slices
    for (int s = tid; s < 1024; s += 256) {
        float acc = 0.f;
        for (int t = 0; t < TILES_; ++t) {
            const float* pp = p1 + (size_t)t * SST_;
            acc += pp[s] + pp[1024 + s] + pp[2048 + s] + pp[3072 + s];
        }
        st[s] = acc;
    }
    // GZ row k, S, Gs_k
    if (tid < 32) {
        float a1 = 0.f, a2 = 0.f, a3 = 0.f;
        for (int t = 0; t < TILES_; ++t) {
            const float* pp = p1 + (size_t)t * SST_;
            a1 += pp[GZOFF_ + k * 32 + tid];
            a2 += pp[SOFF_ + tid];
            if (tid == 0) a3 += pp[GSOFF_ + k];
        }
        st[1024 + tid] = a1;
        st[1056 + tid] = a2;
        if (tid == 0) st[1088] = a3;
    }
    __syncthreads();
    if (tid >= 32) return;

    const float Gs = st[1088];

    // mu = GZ/(Gs+eps), then L2-normalize over channels
    float m = st[1024 + l] / (Gs + EPS_);
    float nrm = sqrtf(wsum(m * m));
    m = m / (EPS_ + nrm);
    mu[l] = m; Sv[l] = st[1056 + l];
    __syncwarp();

    // cov = ZZ - mu S^T - S mu^T + hw mu mu^T
    #pragma unroll 1
    for (int i = 0; i < 32; ++i)
        A[i][l] = st[i * 32 + l] - mu[i] * Sv[l] - m * Sv[i] + 65536.0f * mu[i] * m;
    __syncwarp();

    // diag += max(diag, eps)
    {
        float dg = A[l][l];
        A[l][l] = dg + fmaxf(dg, EPS_);
    }
    __syncwarp();

    // Frobenius normalize
    float sq = 0.f;
    for (int i = 0; i < 32; ++i) sq += A[i][l] * A[i][l];
    float fro = sqrtf(wsum(sq));
    float sc = 1.0f / (EPS_ + fro);
    for (int i = 0; i < 32; ++i) A[i][l] *= sc;
    __syncwarp();

    // Cholesky (lower, in place)
    for (int j = 0; j < 32; ++j) {
        if (l == 0) A[j][j] = sqrtf(A[j][j]);
        __syncwarp();
        float inv = 1.0f / A[j][j];
        if (l > j) A[l][j] *= inv;
        __syncwarp();
        for (int m2 = j + 1; m2 < 32; ++m2) {
            float lmj = A[m2][j];
            if (l >= m2) A[l][m2] = fmaf(-A[l][j], lmj, A[l][m2]);
        }
        __syncwarp();
    }
    float logdet2 = 2.0f * wsum(logf(A[l][l]));

    // Ai = L^-1 (lower); lane l owns column l
    for (int i = 0; i < 32; ++i) Ai[i][l] = 0.0f;
    __syncwarp();
    Ai[l][l] = 1.0f / A[l][l];
    for (int i = l + 1; i < 32; ++i) {
        float s = 0.f;
        for (int m2 = l; m2 < i; ++m2) s = fmaf(A[i][m2], Ai[m2][l], s);
        Ai[i][l] = -s / A[i][i];
    }
    __syncwarp();

    // P = Ai^T Ai
    for (int i = 0; i < 32; ++i) {
        float s = 0.f;
        for (int m2 = 0; m2 < 32; ++m2) s = fmaf(Ai[m2][i], Ai[m2][l], s);
        Pm[i][l] = s;
    }
    __syncwarp();

    // q = P mu, r = mu^T P mu
    float q = 0.f;
    for (int j = 0; j < 32; ++j) q = fmaf(Pm[l][j], mu[j], q);
    float r = wsum(mu[l] * q);

    // pack: upper triangle, halved diagonal, zero below
    float* Pd = g_P + (size_t)bk * (C_ * C_);
    for (int i = 0; i < 32; ++i) {
        float v = (l < i) ? 0.0f : ((l == i) ? 0.5f * Pm[i][i] : Pm[i][l]);
        Pd[i * 32 + l] = v;
    }
    g_Hb[bk * C_ + l] = -q;
    if (l == 0) {
        float phi = Gs / 65536.0f;
        g_Ck[bk] = phi - 0.5f * (CLOG2PI_ + logdet2 + r);
    }
}

// =====================================================================
// Kernel 3 (R8-proven): packed-f32x2 quadratic form, CHANNEL-pair
// packing; 2 pixels per thread share every P load (plain float4 LDS).
// =====================================================================
__global__ __launch_bounds__(256, 2) void k_maha(const float* __restrict__ z)
{
    const int chunk = blockIdx.x;
    const int b     = blockIdx.y;
    const int tid   = threadIdx.x;
    const int wid   = tid >> 5, lid = tid & 31;

    __shared__ __align__(16) float Ps[K_ * 1024];   // 20KB plain P rows
    __shared__ __align__(16) float H2[K_ * 64];     // (H_{2i},0,H_{2i+1},0) x16 per k
    __shared__ float rmx[8 * K_], rsm[8 * K_];

    const float4* Pb4 = reinterpret_cast<const float4*>(g_P + (size_t)b * K_ * 1024);
    float4* Ps4 = reinterpret_cast<float4*>(Ps);
    #pragma unroll
    for (int r = 0; r < K_; ++r) Ps4[tid + r * 256] = Pb4[tid + r * 256];
    if (tid < K_ * 16) {
        const int k = tid / 16, i = tid % 16;
        const float* Hk = g_Hb + (b * K_ + k) * 32;
        float4 h;
        h.x = Hk[2 * i]; h.y = 0.f; h.z = Hk[2 * i + 1]; h.w = 0.f;
        *reinterpret_cast<float4*>(&H2[k * 64 + 4 * i]) = h;
    }
    __syncthreads();

    const float* zb = z + (size_t)b * C_ * HW_;
    const int n2 = chunk * 512 + tid * 2;

    // zA[i] = (z_{2i}, z_{2i+1}) of pixel0; zB[i] same for pixel1
    u64 zA[16], zB[16];
    #pragma unroll 4
    for (int i = 0; i < 16; ++i) {
        const u64 A  = *reinterpret_cast<const u64*>(zb + (size_t)(2 * i)     * HW_ + n2);
        const u64 Bv = *reinterpret_cast<const u64*>(zb + (size_t)(2 * i + 1) * HW_ + n2);
        float a0, b0, a1, b1;
        unpack2(A,  a0, b0);
        unpack2(Bv, a1, b1);
        zA[i] = pack2(a0, a1);
        zB[i] = pack2(b0, b1);
    }

    float mxk[K_], smk[K_];

    #pragma unroll 1
    for (int k = 0; k < K_; ++k) {
        const float* Pk = &Ps[k * 1024];
        const u64* H2k = reinterpret_cast<const u64*>(&H2[k * 64]);
        u64 s0 = 0ull, s1 = 0ull;
        #pragma unroll
        for (int i = 0; i < 16; ++i) {
            const int c0 = 2 * i, c1 = c0 + 1;
            const int jj0 = i & ~1;
            const u64 ha = H2k[2 * i];
            const u64 hb = H2k[2 * i + 1];
            u64 ta0 = ha, ta1 = ha;
            u64 tb0 = hb, tb1 = hb;
            const u64* rowA = reinterpret_cast<const u64*>(Pk + c0 * 32);
            const u64* rowB = reinterpret_cast<const u64*>(Pk + c1 * 32);
            #pragma unroll
            for (int jj = jj0; jj < 16; jj += 2) {
                const ulonglong2 pa = *reinterpret_cast<const ulonglong2*>(rowA + jj);
                const ulonglong2 pb = *reinterpret_cast<const ulonglong2*>(rowB + jj);
                ta0 = fma2(pa.x, zA[jj],     ta0);
                ta1 = fma2(pa.x, zB[jj],     ta1);
                tb0 = fma2(pb.x, zA[jj],     tb0);
                tb1 = fma2(pb.x, zB[jj],     tb1);
                ta0 = fma2(pa.y, zA[jj + 1], ta0);
                ta1 = fma2(pa.y, zB[jj + 1], ta1);
                tb0 = fma2(pb.y, zA[jj + 1], tb0);
                tb1 = fma2(pb.y, zB[jj + 1], tb1);
            }
            float x0, x1, y0, y1, u0, u1, v0, v1;
            unpack2(ta0, x0, x1);
            unpack2(tb0, y0, y1);
            unpack2(ta1, u0, u1);
            unpack2(tb1, v0, v1);
            const u64 T0 = pack2(x0 + x1, y0 + y1);
            const u64 T1 = pack2(u0 + u1, v0 + v1);
            s0 = fma2(zA[i], T0, s0);
            s1 = fma2(zB[i], T1, s1);
        }
        float e0, e1;
        unpack2(s0, e0, e1); const float v0 = -(e0 + e1);
        unpack2(s1, e0, e1); const float v1 = -(e0 + e1);
        const float m = fmaxf(v0, v1);
        mxk[k] = m;
        smk[k] = __expf(v0 - m) + __expf(v1 - m);
    }

    // warp reduce (logsumexp-merge), then cross-warp via smem
    #pragma unroll
    for (int k = 0; k < K_; ++k) {
        float m = mxk[k], s = smk[k];
        #pragma unroll
        for (int o = 16; o; o >>= 1) {
            float m2 = __shfl_xor_sync(0xffffffffu, m, o);
            float s2 = __shfl_xor_sync(0xffffffffu, s, o);
            float nm = fmaxf(m, m2);
            s = s * __expf(m - nm) + s2 * __expf(m2 - nm);
            m = nm;
        }
        if (lid == 0) { rmx[wid * K_ + k] = m; rsm[wid * K_ + k] = s; }
    }
    __syncthreads();
    if (tid < K_) {
        float m = rmx[tid], s = rsm[tid];
        #pragma unroll
        for (int w2 = 1; w2 < 8; ++w2) {
            float m2 = rmx[w2 * K_ + tid], s2 = rsm[w2 * K_ + tid];
            float nm = fmaxf(m, m2);
            s = s * __expf(m - nm) + s2 * __expf(m2 - nm);
            m = nm;
        }
        float* o = g_part2 + (size_t)((b * K_ + tid) * CHUNKS_ + chunk) * 2;
        o[0] = m; o[1] = s;
    }
}

// =====================================================================
// Kernel 4 (R8-proven): combine chunk partials -> energy scalar.
// =====================================================================
__global__ __launch_bounds__(1024) void k_final(float* __restrict__ out)
{
    __shared__ float vals[B_ * K_];
    const int tid = threadIdx.x, w = tid >> 5, lid = tid & 31;

    for (int bk = w; bk < B_ * K_; bk += 32) {
        float m = -CUDART_INF_F, s = 0.0f;
        for (int c = lid; c < CHUNKS_; c += 32) {
            const float* o = g_part2 + (size_t)(bk * CHUNKS_ + c) * 2;
            const float m2 = o[0], s2 = o[1];
            const float nm = fmaxf(m, m2);
            s = s * __expf(m - nm) + s2 * __expf(m2 - nm);
            m = nm;
        }
        #pragma unroll
        for (int o = 16; o; o >>= 1) {
            const float m2 = __shfl_xor_sync(0xffffffffu, m, o);
            const float s2 = __shfl_xor_sync(0xffffffffu, s, o);
            const float nm = fmaxf(m, m2);
            s = s * __expf(m - nm) + s2 * __expf(m2 - nm);
            m = nm;
        }
        if (lid == 0) vals[bk] = g_Ck[bk] + m + logf(s);
    }
    __syncthreads();
    if (tid == 0) {
        float acc = 0.f;
        #pragma unroll
        for (int t = 0; t < B_ * K_; ++t) acc += vals[t];
        out[0] = -(acc / 40.0f) / 65536.0f;
    }
}

// =====================================================================
extern "C" void kernel_launch(void* const* d_in, const int* in_sizes, int n_in,
                              void* d_out, int out_size)
{
    (void)in_sizes; (void)n_in; (void)out_size;
    const float* z = (const float*)d_in[0];
    const float* g = (const float*)d_in[1];

    k_stats <<<dim3(TILES_, B_), 256>>>(z, g);
    k_prep  <<<B_ * K_, 256>>>();
    k_maha  <<<dim3(CHUNKS_, B_), 256>>>(z);
    k_final <<<1, 1024>>>((float*)d_out);
}

// round 14
// speedup vs baseline: 1.1714x; 1.0186x over previous
#include <cuda_runtime.h>
#include <math_constants.h>
#include <math.h>

#define B_      8
#define C_      32
#define K_      5
#define HW_     65536
#define TILES_  32
#define TPX_    2048
#define SST_    (4*1024 + 32*5 + 32 + 5 + 27)   // 4 ZZ team slices + GZ + S + Gs
#define ZZOFF_  0
#define GZOFF_  4096
#define SOFF_   (4096 + 160)
#define GSOFF_  (4096 + 192)
#define CHUNKS_ 128
#define EPS_    1e-6f
#define CLOG2PI_ (32.0f * 1.8378770664093453f)

typedef unsigned long long u64;

// ---- scratch (static device globals; no allocation) ----
__device__ float g_part1[B_ * TILES_ * SST_];
__device__ float g_zz[B_ * C_ * C_];         // per-b reduced ZZ
__device__ float g_P[B_ * K_ * C_ * C_];     // packed upper-tri P, diag halved, lower zero
__device__ float g_Hb[B_ * K_ * C_];         // -q = -(P mu)
__device__ float g_Ck[B_ * K_];              // phi - 0.5*(c*log2pi + logdet + r)
__device__ float g_part2[B_ * K_ * CHUNKS_ * 2];

// ---- packed f32x2 helpers (sm_103a FFMA2 path, PTX-only) ----
__device__ __forceinline__ u64 fma2(u64 a, u64 b, u64 c) {
    u64 d;
    asm("fma.rn.f32x2 %0, %1, %2, %3;" : "=l"(d) : "l"(a), "l"(b), "l"(c));
    return d;
}
__device__ __forceinline__ u64 pack2(float lo, float hi) {
    u64 d;
    asm("mov.b64 %0, {%1, %2};" : "=l"(d) : "f"(lo), "f"(hi));
    return d;
}
__device__ __forceinline__ void unpack2(u64 v, float& lo, float& hi) {
    asm("mov.b64 {%0, %1}, %2;" : "=f"(lo), "=f"(hi) : "l"(v));
}

// =====================================================================
// Kernel 1 (R13): per-(b,tile) partial stats with LDG prefetch pipeline.
// =====================================================================
__global__ __launch_bounds__(256, 2) void k_stats(const float* __restrict__ z,
                                                  const float* __restrict__ g)
{
    const int tile = blockIdx.x, b = blockIdx.y;
    const int tid = threadIdx.x, w = tid >> 5, l = tid & 31;
    __shared__ float zs[256][36];   // pixel-major, float4-aligned rows
    __shared__ float gs[256][8];

    const float* zb = z + (size_t)b * C_ * HW_;
    const float* gb = g + (size_t)b * K_ * HW_;
    const int base0 = tile * TPX_;

    const int team = tid >> 6;
    const int thr  = tid & 63;
    const int ti   = thr >> 3, tj = thr & 7;

    float acc[4][4];
    #pragma unroll
    for (int u = 0; u < 4; ++u)
        #pragma unroll
        for (int v = 0; v < 4; ++v) acc[u][v] = 0.f;
    float bg0 = 0.f, bg1 = 0.f, bg2 = 0.f, bg3 = 0.f, bg4 = 0.f;
    float bs = 0.f;
    float bgs0 = 0.f, bgs1 = 0.f, bgs2 = 0.f, bgs3 = 0.f, bgs4 = 0.f;

    // prefetch registers for the NEXT chunk
    float pz[32], pg[5];
    {
        const int base = base0 + tid;
        #pragma unroll
        for (int c = 0; c < 32; ++c) pz[c] = zb[(size_t)c * HW_ + base];
        #pragma unroll
        for (int r = 0; r < 5; ++r) pg[r] = gb[(size_t)r * HW_ + base];
    }

    #pragma unroll 1
    for (int ch = 0; ch < 8; ++ch) {
        // store prefetched chunk ch to smem
        #pragma unroll
        for (int c4 = 0; c4 < 8; ++c4) {
            float4 v;
            v.x = pz[4 * c4 + 0];
            v.y = pz[4 * c4 + 1];
            v.z = pz[4 * c4 + 2];
            v.w = pz[4 * c4 + 3];
            *reinterpret_cast<float4*>(&zs[tid][4 * c4]) = v;
        }
        {
            float4 gv;
            gv.x = pg[0]; gv.y = pg[1]; gv.z = pg[2]; gv.w = pg[3];
            *reinterpret_cast<float4*>(&gs[tid][0]) = gv;
            gs[tid][4] = pg[4];
        }
        __syncthreads();

        // issue LDGs for chunk ch+1 NOW; compute below hides the latency
        if (ch < 7) {
            const int base = base0 + ((ch + 1) << 8) + tid;
            #pragma unroll
            for (int c = 0; c < 32; ++c) pz[c] = zb[(size_t)c * HW_ + base];
            #pragma unroll
            for (int r = 0; r < 5; ++r) pg[r] = gb[(size_t)r * HW_ + base];
        }

        // phase A: SYRK over this team's 64 pixels
        const int x0 = team << 6;
        #pragma unroll 2
        for (int x = x0; x < x0 + 64; ++x) {
            const float4 a  = *reinterpret_cast<const float4*>(&zs[x][4 * ti]);
            const float4 bb = *reinterpret_cast<const float4*>(&zs[x][4 * tj]);
            acc[0][0] = fmaf(a.x, bb.x, acc[0][0]);
            acc[0][1] = fmaf(a.x, bb.y, acc[0][1]);
            acc[0][2] = fmaf(a.x, bb.z, acc[0][2]);
            acc[0][3] = fmaf(a.x, bb.w, acc[0][3]);
            acc[1][0] = fmaf(a.y, bb.x, acc[1][0]);
            acc[1][1] = fmaf(a.y, bb.y, acc[1][1]);
            acc[1][2] = fmaf(a.y, bb.z, acc[1][2]);
            acc[1][3] = fmaf(a.y, bb.w, acc[1][3]);
            acc[2][0] = fmaf(a.z, bb.x, acc[2][0]);
            acc[2][1] = fmaf(a.z, bb.y, acc[2][1]);
            acc[2][2] = fmaf(a.z, bb.z, acc[2][2]);
            acc[2][3] = fmaf(a.z, bb.w, acc[2][3]);
            acc[3][0] = fmaf(a.w, bb.x, acc[3][0]);
            acc[3][1] = fmaf(a.w, bb.y, acc[3][1]);
            acc[3][2] = fmaf(a.w, bb.z, acc[3][2]);
            acc[3][3] = fmaf(a.w, bb.w, acc[3][3]);
        }

        // phase B: this warp's 32 pixels, all 5 g rows
        const int xb = w << 5;
        #pragma unroll 4
        for (int xx = 0; xx < 32; ++xx) {
            const int x = xb + xx;
            const float zv = zs[x][l];
            const float4 g4 = *reinterpret_cast<const float4*>(&gs[x][0]);
            const float g5 = gs[x][4];
            bg0 = fmaf(g4.x, zv, bg0);
            bg1 = fmaf(g4.y, zv, bg1);
            bg2 = fmaf(g4.z, zv, bg2);
            bg3 = fmaf(g4.w, zv, bg3);
            bg4 = fmaf(g5,   zv, bg4);
            bs += zv;
            bgs0 += g4.x; bgs1 += g4.y; bgs2 += g4.z; bgs3 += g4.w; bgs4 += g5;
        }
        __syncthreads();   // all reads done before next iteration's STS
    }

    float* p = g_part1 + (size_t)(b * TILES_ + tile) * SST_;
    #pragma unroll
    for (int u = 0; u < 4; ++u)
        #pragma unroll
        for (int v = 0; v < 4; ++v)
            p[ZZOFF_ + team * 1024 + (4 * ti + u) * 32 + (4 * tj + v)] = acc[u][v];

    // cross-warp reduce GZ/S/Gs (alias scratch into gs; it is dead now)
    float* red = &gs[0][0];
    red[(w * 5 + 0) * 32 + l] = bg0;
    red[(w * 5 + 1) * 32 + l] = bg1;
    red[(w * 5 + 2) * 32 + l] = bg2;
    red[(w * 5 + 3) * 32 + l] = bg3;
    red[(w * 5 + 4) * 32 + l] = bg4;
    red[1280 + w * 32 + l] = bs;
    if (l == 0) {
        red[1536 + w * 5 + 0] = bgs0;
        red[1536 + w * 5 + 1] = bgs1;
        red[1536 + w * 5 + 2] = bgs2;
        red[1536 + w * 5 + 3] = bgs3;
        red[1536 + w * 5 + 4] = bgs4;
    }
    __syncthreads();
    if (w < 5) {
        float a = 0.f;
        #pragma unroll
        for (int w2 = 0; w2 < 8; ++w2) a += red[(w2 * 5 + w) * 32 + l];
        p[GZOFF_ + w * 32 + l] = a;
    } else if (w == 5) {
        float a = 0.f;
        #pragma unroll
        for (int w2 = 0; w2 < 8; ++w2) a += red[1280 + w2 * 32 + l];
        p[SOFF_ + l] = a;
    } else if (w == 6 && l < 5) {
        float a = 0.f;
        #pragma unroll
        for (int w2 = 0; w2 < 8; ++w2) a += red[1536 + w2 * 5 + l];
        p[GSOFF_ + l] = a;
    }
}

// =====================================================================
// Kernel 2a: per-b ZZ reduction (32 tiles x 4 team slices -> 1024),
// done ONCE per b (32 blocks) instead of 5x redundantly inside prep.
// =====================================================================
__global__ __launch_bounds__(256) void k_zzred()
{
    const int b = blockIdx.x, seg = blockIdx.y;
    const int s = seg * 256 + threadIdx.x;
    const float* p1 = g_part1 + (size_t)b * TILES_ * SST_;
    float acc = 0.f;
    for (int t = 0; t < TILES_; ++t) {
        const float* pp = p1 + (size_t)t * SST_;
        acc += pp[s] + pp[1024 + s] + pp[2048 + s] + pp[3072 + s];
    }
    g_zz[b * 1024 + s] = acc;
}

__device__ __forceinline__ float wsum(float v)
{
    #pragma unroll
    for (int o = 16; o; o >>= 1) v += __shfl_xor_sync(0xffffffffu, v, o);
    return v;
}

// =====================================================================
// Kernel 2b: per-(b,k) block of 256 threads: ZZ read from g_zz (4KB),
// GZ/S/Gs reduced over tiles (25KB), then warp 0 factorizes.
// =====================================================================
__global__ __launch_bounds__(256) void k_prep()
{
    const int bk = blockIdx.x;
    const int b = bk / K_, k = bk % K_;
    const int tid = threadIdx.x, l = tid & 31;
    __shared__ float st[1090];          // ZZ(1024) GZ_k(32) S(32) Gs_k(1)
    __shared__ float A [32][33];
    __shared__ float Ai[32][33];
    __shared__ float Pm[32][33];
    __shared__ float mu[32], Sv[32];

    const float* p1 = g_part1 + (size_t)b * TILES_ * SST_;

    // ZZ: pre-reduced, just read
    #pragma unroll
    for (int i = 0; i < 4; ++i)
        st[tid + i * 256] = g_zz[b * 1024 + tid + i * 256];
    // GZ row k, S, Gs_k reduced over tiles
    if (tid < 32) {
        float a1 = 0.f, a2 = 0.f, a3 = 0.f;
        for (int t = 0; t < TILES_; ++t) {
            const float* pp = p1 + (size_t)t * SST_;
            a1 += pp[GZOFF_ + k * 32 + tid];
            a2 += pp[SOFF_ + tid];
            if (tid == 0) a3 += pp[GSOFF_ + k];
        }
        st[1024 + tid] = a1;
        st[1056 + tid] = a2;
        if (tid == 0) st[1088] = a3;
    }
    __syncthreads();
    if (tid >= 32) return;

    const float Gs = st[1088];

    // mu = GZ/(Gs+eps), then L2-normalize over channels
    float m = st[1024 + l] / (Gs + EPS_);
    float nrm = sqrtf(wsum(m * m));
    m = m / (EPS_ + nrm);
    mu[l] = m; Sv[l] = st[1056 + l];
    __syncwarp();

    // cov = ZZ - mu S^T - S mu^T + hw mu mu^T
    #pragma unroll 1
    for (int i = 0; i < 32; ++i)
        A[i][l] = st[i * 32 + l] - mu[i] * Sv[l] - m * Sv[i] + 65536.0f * mu[i] * m;
    __syncwarp();

    // diag += max(diag, eps)
    {
        float dg = A[l][l];
        A[l][l] = dg + fmaxf(dg, EPS_);
    }
    __syncwarp();

    // Frobenius normalize
    float sq = 0.f;
    for (int i = 0; i < 32; ++i) sq += A[i][l] * A[i][l];
    float fro = sqrtf(wsum(sq));
    float sc = 1.0f / (EPS_ + fro);
    for (int i = 0; i < 32; ++i) A[i][l] *= sc;
    __syncwarp();

    // Cholesky (lower, in place)
    for (int j = 0; j < 32; ++j) {
        if (l == 0) A[j][j] = sqrtf(A[j][j]);
        __syncwarp();
        float inv = 1.0f / A[j][j];
        if (l > j) A[l][j] *= inv;
        __syncwarp();
        for (int m2 = j + 1; m2 < 32; ++m2) {
            float lmj = A[m2][j];
            if (l >= m2) A[l][m2] = fmaf(-A[l][j], lmj, A[l][m2]);
        }
        __syncwarp();
    }
    float logdet2 = 2.0f * wsum(logf(A[l][l]));

    // Ai = L^-1 (lower); lane l owns column l
    for (int i = 0; i < 32; ++i) Ai[i][l] = 0.0f;
    __syncwarp();
    Ai[l][l] = 1.0f / A[l][l];
    for (int i = l + 1; i < 32; ++i) {
        float s = 0.f;
        for (int m2 = l; m2 < i; ++m2) s = fmaf(A[i][m2], Ai[m2][l], s);
        Ai[i][l] = -s / A[i][i];
    }
    __syncwarp();

    // P = Ai^T Ai
    for (int i = 0; i < 32; ++i) {
        float s = 0.f;
        for (int m2 = 0; m2 < 32; ++m2) s = fmaf(Ai[m2][i], Ai[m2][l], s);
        Pm[i][l] = s;
    }
    __syncwarp();

    // q = P mu, r = mu^T P mu
    float q = 0.f;
    for (int j = 0; j < 32; ++j) q = fmaf(Pm[l][j], mu[j], q);
    float r = wsum(mu[l] * q);

    // pack: upper triangle, halved diagonal, zero below
    float* Pd = g_P + (size_t)bk * (C_ * C_);
    for (int i = 0; i < 32; ++i) {
        float v = (l < i) ? 0.0f : ((l == i) ? 0.5f * Pm[i][i] : Pm[i][l]);
        Pd[i * 32 + l] = v;
    }
    g_Hb[bk * C_ + l] = -q;
    if (l == 0) {
        float phi = Gs / 65536.0f;
        g_Ck[bk] = phi - 0.5f * (CLOG2PI_ + logdet2 + r);
    }
}

// =====================================================================
// Kernel 3 (R8-proven): packed-f32x2 quadratic form, CHANNEL-pair
// packing; 2 pixels per thread share every P load (plain float4 LDS).
// =====================================================================
__global__ __launch_bounds__(256, 2) void k_maha(const float* __restrict__ z)
{
    const int chunk = blockIdx.x;
    const int b     = blockIdx.y;
    const int tid   = threadIdx.x;
    const int wid   = tid >> 5, lid = tid & 31;

    __shared__ __align__(16) float Ps[K_ * 1024];   // 20KB plain P rows
    __shared__ __align__(16) float H2[K_ * 64];     // (H_{2i},0,H_{2i+1},0) x16 per k
    __shared__ float rmx[8 * K_], rsm[8 * K_];

    const float4* Pb4 = reinterpret_cast<const float4*>(g_P + (size_t)b * K_ * 1024);
    float4* Ps4 = reinterpret_cast<float4*>(Ps);
    #pragma unroll
    for (int r = 0; r < K_; ++r) Ps4[tid + r * 256] = Pb4[tid + r * 256];
    if (tid < K_ * 16) {
        const int k = tid / 16, i = tid % 16;
        const float* Hk = g_Hb + (b * K_ + k) * 32;
        float4 h;
        h.x = Hk[2 * i]; h.y = 0.f; h.z = Hk[2 * i + 1]; h.w = 0.f;
        *reinterpret_cast<float4*>(&H2[k * 64 + 4 * i]) = h;
    }
    __syncthreads();

    const float* zb = z + (size_t)b * C_ * HW_;
    const int n2 = chunk * 512 + tid * 2;

    // zA[i] = (z_{2i}, z_{2i+1}) of pixel0; zB[i] same for pixel1
    u64 zA[16], zB[16];
    #pragma unroll 4
    for (int i = 0; i < 16; ++i) {
        const u64 A  = *reinterpret_cast<const u64*>(zb + (size_t)(2 * i)     * HW_ + n2);
        const u64 Bv = *reinterpret_cast<const u64*>(zb + (size_t)(2 * i + 1) * HW_ + n2);
        float a0, b0, a1, b1;
        unpack2(A,  a0, b0);
        unpack2(Bv, a1, b1);
        zA[i] = pack2(a0, a1);
        zB[i] = pack2(b0, b1);
    }

    float mxk[K_], smk[K_];

    #pragma unroll 1
    for (int k = 0; k < K_; ++k) {
        const float* Pk = &Ps[k * 1024];
        const u64* H2k = reinterpret_cast<const u64*>(&H2[k * 64]);
        u64 s0 = 0ull, s1 = 0ull;
        #pragma unroll
        for (int i = 0; i < 16; ++i) {
            const int c0 = 2 * i, c1 = c0 + 1;
            const int jj0 = i & ~1;
            const u64 ha = H2k[2 * i];
            const u64 hb = H2k[2 * i + 1];
            u64 ta0 = ha, ta1 = ha;
            u64 tb0 = hb, tb1 = hb;
            const u64* rowA = reinterpret_cast<const u64*>(Pk + c0 * 32);
            const u64* rowB = reinterpret_cast<const u64*>(Pk + c1 * 32);
            #pragma unroll
            for (int jj = jj0; jj < 16; jj += 2) {
                const ulonglong2 pa = *reinterpret_cast<const ulonglong2*>(rowA + jj);
                const ulonglong2 pb = *reinterpret_cast<const ulonglong2*>(rowB + jj);
                ta0 = fma2(pa.x, zA[jj],     ta0);
                ta1 = fma2(pa.x, zB[jj],     ta1);
                tb0 = fma2(pb.x, zA[jj],     tb0);
                tb1 = fma2(pb.x, zB[jj],     tb1);
                ta0 = fma2(pa.y, zA[jj + 1], ta0);
                ta1 = fma2(pa.y, zB[jj + 1], ta1);
                tb0 = fma2(pb.y, zA[jj + 1], tb0);
                tb1 = fma2(pb.y, zB[jj + 1], tb1);
            }
            float x0, x1, y0, y1, u0, u1, v0, v1;
            unpack2(ta0, x0, x1);
            unpack2(tb0, y0, y1);
            unpack2(ta1, u0, u1);
            unpack2(tb1, v0, v1);
            const u64 T0 = pack2(x0 + x1, y0 + y1);
            const u64 T1 = pack2(u0 + u1, v0 + v1);
            s0 = fma2(zA[i], T0, s0);
            s1 = fma2(zB[i], T1, s1);
        }
        float e0, e1;
        unpack2(s0, e0, e1); const float v0 = -(e0 + e1);
        unpack2(s1, e0, e1); const float v1 = -(e0 + e1);
        const float m = fmaxf(v0, v1);
        mxk[k] = m;
        smk[k] = __expf(v0 - m) + __expf(v1 - m);
    }

    // warp reduce (logsumexp-merge), then cross-warp via smem
    #pragma unroll
    for (int k = 0; k < K_; ++k) {
        float m = mxk[k], s = smk[k];
        #pragma unroll
        for (int o = 16; o; o >>= 1) {
            float m2 = __shfl_xor_sync(0xffffffffu, m, o);
            float s2 = __shfl_xor_sync(0xffffffffu, s, o);
            float nm = fmaxf(m, m2);
            s = s * __expf(m - nm) + s2 * __expf(m2 - nm);
            m = nm;
        }
        if (lid == 0) { rmx[wid * K_ + k] = m; rsm[wid * K_ + k] = s; }
    }
    __syncthreads();
    if (tid < K_) {
        float m = rmx[tid], s = rsm[tid];
        #pragma unroll
        for (int w2 = 1; w2 < 8; ++w2) {
            float m2 = rmx[w2 * K_ + tid], s2 = rsm[w2 * K_ + tid];
            float nm = fmaxf(m, m2);
            s = s * __expf(m - nm) + s2 * __expf(m2 - nm);
            m = nm;
        }
        float* o = g_part2 + (size_t)((b * K_ + tid) * CHUNKS_ + chunk) * 2;
        o[0] = m; o[1] = s;
    }
}

// =====================================================================
// Kernel 4 (R8-proven): combine chunk partials -> energy scalar.
// =====================================================================
__global__ __launch_bounds__(1024) void k_final(float* __restrict__ out)
{
    __shared__ float vals[B_ * K_];
    const int tid = threadIdx.x, w = tid >> 5, lid = tid & 31;

    for (int bk = w; bk < B_ * K_; bk += 32) {
        float m = -CUDART_INF_F, s = 0.0f;
        for (int c = lid; c < CHUNKS_; c += 32) {
            const float* o = g_part2 + (size_t)(bk * CHUNKS_ + c) * 2;
            const float m2 = o[0], s2 = o[1];
            const float nm = fmaxf(m, m2);
            s = s * __expf(m - nm) + s2 * __expf(m2 - nm);
            m = nm;
        }
        #pragma unroll
        for (int o = 16; o; o >>= 1) {
            const float m2 = __shfl_xor_sync(0xffffffffu, m, o);
            const float s2 = __shfl_xor_sync(0xffffffffu, s, o);
            const float nm = fmaxf(m, m2);
            s = s * __expf(m - nm) + s2 * __expf(m2 - nm);
            m = nm;
        }
        if (lid == 0) vals[bk] = g_Ck[bk] + m + logf(s);
    }
    __syncthreads();
    if (tid == 0) {
        float acc = 0.f;
        #pragma unroll
        for (int t = 0; t < B_ * K_; ++t) acc += vals[t];
        out[0] = -(acc / 40.0f) / 65536.0f;
    }
}

// =====================================================================
extern "C" void kernel_launch(void* const* d_in, const int* in_sizes, int n_in,
                              void* d_out, int out_size)
{
    (void)in_sizes; (void)n_in; (void)out_size;
    const float* z = (const float*)d_in[0];
    const float* g = (const float*)d_in[1];

    k_stats <<<dim3(TILES_, B_), 256>>>(z, g);
    k_zzred <<<dim3(B_, 4), 256>>>();
    k_prep  <<<B_ * K_, 256>>>();
    k_maha  <<<dim3(CHUNKS_, B_), 256>>>(z);
    k_final <<<1, 1024>>>((float*)d_out);
}

// round 15
// speedup vs baseline: 1.2273x; 1.0477x over previous
#include <cuda_runtime.h>
#include <math_constants.h>
#include <math.h>

#define B_      8
#define C_      32
#define K_      5
#define HW_     65536
#define TILES_  32
#define TPX_    2048
#define SST_    (4*1024 + 32*5 + 32 + 5 + 27)   // 4 ZZ team slices + GZ + S + Gs
#define ZZOFF_  0
#define GZOFF_  4096
#define SOFF_   (4096 + 160)
#define GSOFF_  (4096 + 192)
#define CHUNKS_ 128
#define EPS_    1e-6f
#define CLOG2PI_ (32.0f * 1.8378770664093453f)

typedef unsigned long long u64;

// ---- scratch (static device globals; no allocation) ----
__device__ float g_part1[B_ * TILES_ * SST_];
__device__ float g_zz[B_ * C_ * C_];         // per-b reduced ZZ
__device__ float g_P[B_ * K_ * C_ * C_];     // packed upper-tri P, diag halved, lower zero
__device__ float g_Hb[B_ * K_ * C_];         // -q = -(P mu)
__device__ float g_Ck[B_ * K_];              // phi - 0.5*(c*log2pi + logdet + r)
__device__ float g_part2[B_ * K_ * CHUNKS_ * 2];

// ---- packed f32x2 helpers (sm_103a FFMA2 path, PTX-only) ----
__device__ __forceinline__ u64 fma2(u64 a, u64 b, u64 c) {
    u64 d;
    asm("fma.rn.f32x2 %0, %1, %2, %3;" : "=l"(d) : "l"(a), "l"(b), "l"(c));
    return d;
}
__device__ __forceinline__ u64 pack2(float lo, float hi) {
    u64 d;
    asm("mov.b64 %0, {%1, %2};" : "=l"(d) : "f"(lo), "f"(hi));
    return d;
}
__device__ __forceinline__ void unpack2(u64 v, float& lo, float& hi) {
    asm("mov.b64 {%0, %1}, %2;" : "=f"(lo), "=f"(hi) : "l"(v));
}

// =====================================================================
// Kernel 1 (R13/R14): per-(b,tile) partial stats with LDG prefetch.
// =====================================================================
__global__ __launch_bounds__(256, 2) void k_stats(const float* __restrict__ z,
                                                  const float* __restrict__ g)
{
    const int tile = blockIdx.x, b = blockIdx.y;
    const int tid = threadIdx.x, w = tid >> 5, l = tid & 31;
    __shared__ float zs[256][36];   // pixel-major, float4-aligned rows
    __shared__ float gs[256][8];

    const float* zb = z + (size_t)b * C_ * HW_;
    const float* gb = g + (size_t)b * K_ * HW_;
    const int base0 = tile * TPX_;

    const int team = tid >> 6;
    const int thr  = tid & 63;
    const int ti   = thr >> 3, tj = thr & 7;

    float acc[4][4];
    #pragma unroll
    for (int u = 0; u < 4; ++u)
        #pragma unroll
        for (int v = 0; v < 4; ++v) acc[u][v] = 0.f;
    float bg0 = 0.f, bg1 = 0.f, bg2 = 0.f, bg3 = 0.f, bg4 = 0.f;
    float bs = 0.f;
    float bgs0 = 0.f, bgs1 = 0.f, bgs2 = 0.f, bgs3 = 0.f, bgs4 = 0.f;

    float pz[32], pg[5];
    {
        const int base = base0 + tid;
        #pragma unroll
        for (int c = 0; c < 32; ++c) pz[c] = zb[(size_t)c * HW_ + base];
        #pragma unroll
        for (int r = 0; r < 5; ++r) pg[r] = gb[(size_t)r * HW_ + base];
    }

    #pragma unroll 1
    for (int ch = 0; ch < 8; ++ch) {
        #pragma unroll
        for (int c4 = 0; c4 < 8; ++c4) {
            float4 v;
            v.x = pz[4 * c4 + 0];
            v.y = pz[4 * c4 + 1];
            v.z = pz[4 * c4 + 2];
            v.w = pz[4 * c4 + 3];
            *reinterpret_cast<float4*>(&zs[tid][4 * c4]) = v;
        }
        {
            float4 gv;
            gv.x = pg[0]; gv.y = pg[1]; gv.z = pg[2]; gv.w = pg[3];
            *reinterpret_cast<float4*>(&gs[tid][0]) = gv;
            gs[tid][4] = pg[4];
        }
        __syncthreads();

        if (ch < 7) {
            const int base = base0 + ((ch + 1) << 8) + tid;
            #pragma unroll
            for (int c = 0; c < 32; ++c) pz[c] = zb[(size_t)c * HW_ + base];
            #pragma unroll
            for (int r = 0; r < 5; ++r) pg[r] = gb[(size_t)r * HW_ + base];
        }

        const int x0 = team << 6;
        #pragma unroll 2
        for (int x = x0; x < x0 + 64; ++x) {
            const float4 a  = *reinterpret_cast<const float4*>(&zs[x][4 * ti]);
            const float4 bb = *reinterpret_cast<const float4*>(&zs[x][4 * tj]);
            acc[0][0] = fmaf(a.x, bb.x, acc[0][0]);
            acc[0][1] = fmaf(a.x, bb.y, acc[0][1]);
            acc[0][2] = fmaf(a.x, bb.z, acc[0][2]);
            acc[0][3] = fmaf(a.x, bb.w, acc[0][3]);
            acc[1][0] = fmaf(a.y, bb.x, acc[1][0]);
            acc[1][1] = fmaf(a.y, bb.y, acc[1][1]);
            acc[1][2] = fmaf(a.y, bb.z, acc[1][2]);
            acc[1][3] = fmaf(a.y, bb.w, acc[1][3]);
            acc[2][0] = fmaf(a.z, bb.x, acc[2][0]);
            acc[2][1] = fmaf(a.z, bb.y, acc[2][1]);
            acc[2][2] = fmaf(a.z, bb.z, acc[2][2]);
            acc[2][3] = fmaf(a.z, bb.w, acc[2][3]);
            acc[3][0] = fmaf(a.w, bb.x, acc[3][0]);
            acc[3][1] = fmaf(a.w, bb.y, acc[3][1]);
            acc[3][2] = fmaf(a.w, bb.z, acc[3][2]);
            acc[3][3] = fmaf(a.w, bb.w, acc[3][3]);
        }

        const int xb = w << 5;
        #pragma unroll 4
        for (int xx = 0; xx < 32; ++xx) {
            const int x = xb + xx;
            const float zv = zs[x][l];
            const float4 g4 = *reinterpret_cast<const float4*>(&gs[x][0]);
            const float g5 = gs[x][4];
            bg0 = fmaf(g4.x, zv, bg0);
            bg1 = fmaf(g4.y, zv, bg1);
            bg2 = fmaf(g4.z, zv, bg2);
            bg3 = fmaf(g4.w, zv, bg3);
            bg4 = fmaf(g5,   zv, bg4);
            bs += zv;
            bgs0 += g4.x; bgs1 += g4.y; bgs2 += g4.z; bgs3 += g4.w; bgs4 += g5;
        }
        __syncthreads();
    }

    float* p = g_part1 + (size_t)(b * TILES_ + tile) * SST_;
    #pragma unroll
    for (int u = 0; u < 4; ++u)
        #pragma unroll
        for (int v = 0; v < 4; ++v)
            p[ZZOFF_ + team * 1024 + (4 * ti + u) * 32 + (4 * tj + v)] = acc[u][v];

    float* red = &gs[0][0];
    red[(w * 5 + 0) * 32 + l] = bg0;
    red[(w * 5 + 1) * 32 + l] = bg1;
    red[(w * 5 + 2) * 32 + l] = bg2;
    red[(w * 5 + 3) * 32 + l] = bg3;
    red[(w * 5 + 4) * 32 + l] = bg4;
    red[1280 + w * 32 + l] = bs;
    if (l == 0) {
        red[1536 + w * 5 + 0] = bgs0;
        red[1536 + w * 5 + 1] = bgs1;
        red[1536 + w * 5 + 2] = bgs2;
        red[1536 + w * 5 + 3] = bgs3;
        red[1536 + w * 5 + 4] = bgs4;
    }
    __syncthreads();
    if (w < 5) {
        float a = 0.f;
        #pragma unroll
        for (int w2 = 0; w2 < 8; ++w2) a += red[(w2 * 5 + w) * 32 + l];
        p[GZOFF_ + w * 32 + l] = a;
    } else if (w == 5) {
        float a = 0.f;
        #pragma unroll
        for (int w2 = 0; w2 < 8; ++w2) a += red[1280 + w2 * 32 + l];
        p[SOFF_ + l] = a;
    } else if (w == 6 && l < 5) {
        float a = 0.f;
        #pragma unroll
        for (int w2 = 0; w2 < 8; ++w2) a += red[1536 + w2 * 5 + l];
        p[GSOFF_ + l] = a;
    }
}

// =====================================================================
// Kernel 2a (R14): per-b ZZ reduction, 32 blocks.
// =====================================================================
__global__ __launch_bounds__(256) void k_zzred()
{
    const int b = blockIdx.x, seg = blockIdx.y;
    const int s = seg * 256 + threadIdx.x;
    const float* p1 = g_part1 + (size_t)b * TILES_ * SST_;
    float acc = 0.f;
    for (int t = 0; t < TILES_; ++t) {
        const float* pp = p1 + (size_t)t * SST_;
        acc += pp[s] + pp[1024 + s] + pp[2048 + s] + pp[3072 + s];
    }
    g_zz[b * 1024 + s] = acc;
}

__device__ __forceinline__ float wsum(float v)
{
    #pragma unroll
    for (int o = 16; o; o >>= 1) v += __shfl_xor_sync(0xffffffffu, v, o);
    return v;
}

// =====================================================================
// Kernel 2b (R14): per-(b,k) block: ZZ read pre-reduced; warp 0
// factorizes (mu, cov, Cholesky, P = L^-T L^-1, q, r, logdet).
// =====================================================================
__global__ __launch_bounds__(256) void k_prep()
{
    const int bk = blockIdx.x;
    const int b = bk / K_, k = bk % K_;
    const int tid = threadIdx.x, l = tid & 31;
    __shared__ float st[1090];          // ZZ(1024) GZ_k(32) S(32) Gs_k(1)
    __shared__ float A [32][33];
    __shared__ float Ai[32][33];
    __shared__ float Pm[32][33];
    __shared__ float mu[32], Sv[32];

    const float* p1 = g_part1 + (size_t)b * TILES_ * SST_;

    #pragma unroll
    for (int i = 0; i < 4; ++i)
        st[tid + i * 256] = g_zz[b * 1024 + tid + i * 256];
    if (tid < 32) {
        float a1 = 0.f, a2 = 0.f, a3 = 0.f;
        for (int t = 0; t < TILES_; ++t) {
            const float* pp = p1 + (size_t)t * SST_;
            a1 += pp[GZOFF_ + k * 32 + tid];
            a2 += pp[SOFF_ + tid];
            if (tid == 0) a3 += pp[GSOFF_ + k];
        }
        st[1024 + tid] = a1;
        st[1056 + tid] = a2;
        if (tid == 0) st[1088] = a3;
    }
    __syncthreads();
    if (tid >= 32) return;

    const float Gs = st[1088];

    float m = st[1024 + l] / (Gs + EPS_);
    float nrm = sqrtf(wsum(m * m));
    m = m / (EPS_ + nrm);
    mu[l] = m; Sv[l] = st[1056 + l];
    __syncwarp();

    #pragma unroll 1
    for (int i = 0; i < 32; ++i)
        A[i][l] = st[i * 32 + l] - mu[i] * Sv[l] - m * Sv[i] + 65536.0f * mu[i] * m;
    __syncwarp();

    {
        float dg = A[l][l];
        A[l][l] = dg + fmaxf(dg, EPS_);
    }
    __syncwarp();

    float sq = 0.f;
    for (int i = 0; i < 32; ++i) sq += A[i][l] * A[i][l];
    float fro = sqrtf(wsum(sq));
    float sc = 1.0f / (EPS_ + fro);
    for (int i = 0; i < 32; ++i) A[i][l] *= sc;
    __syncwarp();

    for (int j = 0; j < 32; ++j) {
        if (l == 0) A[j][j] = sqrtf(A[j][j]);
        __syncwarp();
        float inv = 1.0f / A[j][j];
        if (l > j) A[l][j] *= inv;
        __syncwarp();
        for (int m2 = j + 1; m2 < 32; ++m2) {
            float lmj = A[m2][j];
            if (l >= m2) A[l][m2] = fmaf(-A[l][j], lmj, A[l][m2]);
        }
        __syncwarp();
    }
    float logdet2 = 2.0f * wsum(logf(A[l][l]));

    for (int i = 0; i < 32; ++i) Ai[i][l] = 0.0f;
    __syncwarp();
    Ai[l][l] = 1.0f / A[l][l];
    for (int i = l + 1; i < 32; ++i) {
        float s = 0.f;
        for (int m2 = l; m2 < i; ++m2) s = fmaf(A[i][m2], Ai[m2][l], s);
        Ai[i][l] = -s / A[i][i];
    }
    __syncwarp();

    for (int i = 0; i < 32; ++i) {
        float s = 0.f;
        for (int m2 = 0; m2 < 32; ++m2) s = fmaf(Ai[m2][i], Ai[m2][l], s);
        Pm[i][l] = s;
    }
    __syncwarp();

    float q = 0.f;
    for (int j = 0; j < 32; ++j) q = fmaf(Pm[l][j], mu[j], q);
    float r = wsum(mu[l] * q);

    float* Pd = g_P + (size_t)bk * (C_ * C_);
    for (int i = 0; i < 32; ++i) {
        float v = (l < i) ? 0.0f : ((l == i) ? 0.5f * Pm[i][i] : Pm[i][l]);
        Pd[i * 32 + l] = v;
    }
    g_Hb[bk * C_ + l] = -q;
    if (l == 0) {
        float phi = Gs / 65536.0f;
        g_Ck[bk] = phi - 0.5f * (CLOG2PI_ + logdet2 + r);
    }
}

// =====================================================================
// Kernel 3: packed-f32x2 quadratic form, CHANNEL-pair packing,
// FOUR pixels per thread: every P LDS.128 now feeds 16 fma2 (was 8),
// halving the LDS stream that co-binds with the FMA pipe.
// 128 threads/block, 512-px chunks, 2 blocks/SM (reg cap 256).
// =====================================================================
__global__ __launch_bounds__(128, 2) void k_maha(const float* __restrict__ z)
{
    const int chunk = blockIdx.x;
    const int b     = blockIdx.y;
    const int tid   = threadIdx.x;
    const int wid   = tid >> 5, lid = tid & 31;

    __shared__ __align__(16) float Ps[K_ * 1024];   // 20KB plain P rows
    __shared__ __align__(16) float H2[K_ * 64];     // (H_{2i},0,H_{2i+1},0) x16 per k
    __shared__ float rmx[4 * K_], rsm[4 * K_];

    const float4* Pb4 = reinterpret_cast<const float4*>(g_P + (size_t)b * K_ * 1024);
    float4* Ps4 = reinterpret_cast<float4*>(Ps);
    #pragma unroll
    for (int r = 0; r < K_ * 2; ++r) Ps4[tid + r * 128] = Pb4[tid + r * 128];
    if (tid < K_ * 16) {
        const int k = tid / 16, i = tid % 16;
        const float* Hk = g_Hb + (b * K_ + k) * 32;
        float4 h;
        h.x = Hk[2 * i]; h.y = 0.f; h.z = Hk[2 * i + 1]; h.w = 0.f;
        *reinterpret_cast<float4*>(&H2[k * 64 + 4 * i]) = h;
    }
    __syncthreads();

    const float* zb = z + (size_t)b * C_ * HW_;
    const int n4 = chunk * 512 + tid * 4;

    // zz[p][i] = (z_{2i}, z_{2i+1}) of pixel p (4 adjacent pixels)
    u64 z0[16], z1[16], z2[16], z3[16];
    #pragma unroll 4
    for (int i = 0; i < 16; ++i) {
        const ulonglong2 A2 = *reinterpret_cast<const ulonglong2*>(zb + (size_t)(2 * i)     * HW_ + n4);
        const ulonglong2 B2 = *reinterpret_cast<const ulonglong2*>(zb + (size_t)(2 * i + 1) * HW_ + n4);
        float a0, a1, a2, a3, b0, b1, b2, b3;
        unpack2(A2.x, a0, a1); unpack2(A2.y, a2, a3);
        unpack2(B2.x, b0, b1); unpack2(B2.y, b2, b3);
        z0[i] = pack2(a0, b0);
        z1[i] = pack2(a1, b1);
        z2[i] = pack2(a2, b2);
        z3[i] = pack2(a3, b3);
    }

    float mxk[K_], smk[K_];

    #pragma unroll 1
    for (int k = 0; k < K_; ++k) {
        const float* Pk = &Ps[k * 1024];
        const u64* H2k = reinterpret_cast<const u64*>(&H2[k * 64]);
        u64 s0 = 0ull, s1 = 0ull, s2 = 0ull, s3 = 0ull;
        #pragma unroll
        for (int i = 0; i < 16; ++i) {
            const int c0 = 2 * i, c1 = c0 + 1;
            const int jj0 = i & ~1;
            const u64 ha = H2k[2 * i];
            const u64 hb = H2k[2 * i + 1];
            u64 ta0 = ha, ta1 = ha, ta2 = ha, ta3 = ha;   // row c0 x 4 px
            u64 tb0 = hb, tb1 = hb, tb2 = hb, tb3 = hb;   // row c1 x 4 px
            const u64* rowA = reinterpret_cast<const u64*>(Pk + c0 * 32);
            const u64* rowB = reinterpret_cast<const u64*>(Pk + c1 * 32);
            #pragma unroll
            for (int jj = jj0; jj < 16; jj += 2) {
                const ulonglong2 pa = *reinterpret_cast<const ulonglong2*>(rowA + jj);
                const ulonglong2 pb = *reinterpret_cast<const ulonglong2*>(rowB + jj);
                ta0 = fma2(pa.x, z0[jj],     ta0);
                ta1 = fma2(pa.x, z1[jj],     ta1);
                ta2 = fma2(pa.x, z2[jj],     ta2);
                ta3 = fma2(pa.x, z3[jj],     ta3);
                tb0 = fma2(pb.x, z0[jj],     tb0);
                tb1 = fma2(pb.x, z1[jj],     tb1);
                tb2 = fma2(pb.x, z2[jj],     tb2);
                tb3 = fma2(pb.x, z3[jj],     tb3);
                ta0 = fma2(pa.y, z0[jj + 1], ta0);
                ta1 = fma2(pa.y, z1[jj + 1], ta1);
                ta2 = fma2(pa.y, z2[jj + 1], ta2);
                ta3 = fma2(pa.y, z3[jj + 1], ta3);
                tb0 = fma2(pb.y, z0[jj + 1], tb0);
                tb1 = fma2(pb.y, z1[jj + 1], tb1);
                tb2 = fma2(pb.y, z2[jj + 1], tb2);
                tb3 = fma2(pb.y, z3[jj + 1], tb3);
            }
            float xa, xb2, ya, yb;
            unpack2(ta0, xa, xb2); unpack2(tb0, ya, yb);
            s0 = fma2(z0[i], pack2(xa + xb2, ya + yb), s0);
            unpack2(ta1, xa, xb2); unpack2(tb1, ya, yb);
            s1 = fma2(z1[i], pack2(xa + xb2, ya + yb), s1);
            unpack2(ta2, xa, xb2); unpack2(tb2, ya, yb);
            s2 = fma2(z2[i], pack2(xa + xb2, ya + yb), s2);
            unpack2(ta3, xa, xb2); unpack2(tb3, ya, yb);
            s3 = fma2(z3[i], pack2(xa + xb2, ya + yb), s3);
        }
        float e0, e1;
        unpack2(s0, e0, e1); const float v0 = -(e0 + e1);
        unpack2(s1, e0, e1); const float v1 = -(e0 + e1);
        unpack2(s2, e0, e1); const float v2 = -(e0 + e1);
        unpack2(s3, e0, e1); const float v3 = -(e0 + e1);
        const float m = fmaxf(fmaxf(v0, v1), fmaxf(v2, v3));
        mxk[k] = m;
        smk[k] = __expf(v0 - m) + __expf(v1 - m) + __expf(v2 - m) + __expf(v3 - m);
    }

    // warp reduce (logsumexp-merge), then cross-warp via smem (4 warps)
    #pragma unroll
    for (int k = 0; k < K_; ++k) {
        float m = mxk[k], s = smk[k];
        #pragma unroll
        for (int o = 16; o; o >>= 1) {
            float m2 = __shfl_xor_sync(0xffffffffu, m, o);
            float s2 = __shfl_xor_sync(0xffffffffu, s, o);
            float nm = fmaxf(m, m2);
            s = s * __expf(m - nm) + s2 * __expf(m2 - nm);
            m = nm;
        }
        if (lid == 0) { rmx[wid * K_ + k] = m; rsm[wid * K_ + k] = s; }
    }
    __syncthreads();
    if (tid < K_) {
        float m = rmx[tid], s = rsm[tid];
        #pragma unroll
        for (int w2 = 1; w2 < 4; ++w2) {
            float m2 = rmx[w2 * K_ + tid], s2 = rsm[w2 * K_ + tid];
            float nm = fmaxf(m, m2);
            s = s * __expf(m - nm) + s2 * __expf(m2 - nm);
            m = nm;
        }
        float* o = g_part2 + (size_t)((b * K_ + tid) * CHUNKS_ + chunk) * 2;
        o[0] = m; o[1] = s;
    }
}

// =====================================================================
// Kernel 4 (R8-proven): combine chunk partials -> energy scalar.
// =====================================================================
__global__ __launch_bounds__(1024) void k_final(float* __restrict__ out)
{
    __shared__ float vals[B_ * K_];
    const int tid = threadIdx.x, w = tid >> 5, lid = tid & 31;

    for (int bk = w; bk < B_ * K_; bk += 32) {
        float m = -CUDART_INF_F, s = 0.0f;
        for (int c = lid; c < CHUNKS_; c += 32) {
            const float* o = g_part2 + (size_t)(bk * CHUNKS_ + c) * 2;
            const float m2 = o[0], s2 = o[1];
            const float nm = fmaxf(m, m2);
            s = s * __expf(m - nm) + s2 * __expf(m2 - nm);
            m = nm;
        }
        #pragma unroll
        for (int o = 16; o; o >>= 1) {
            const float m2 = __shfl_xor_sync(0xffffffffu, m, o);
            const float s2 = __shfl_xor_sync(0xffffffffu, s, o);
            const float nm = fmaxf(m, m2);
            s = s * __expf(m - nm) + s2 * __expf(m2 - nm);
            m = nm;
        }
        if (lid == 0) vals[bk] = g_Ck[bk] + m + logf(s);
    }
    __syncthreads();
    if (tid == 0) {
        float acc = 0.f;
        #pragma unroll
        for (int t = 0; t < B_ * K_; ++t) acc += vals[t];
        out[0] = -(acc / 40.0f) / 65536.0f;
    }
}

// =====================================================================
extern "C" void kernel_launch(void* const* d_in, const int* in_sizes, int n_in,
                              void* d_out, int out_size)
{
    (void)in_sizes; (void)n_in; (void)out_size;
    const float* z = (const float*)d_in[0];
    const float* g = (const float*)d_in[1];

    k_stats <<<dim3(TILES_, B_), 256>>>(z, g);
    k_zzred <<<dim3(B_, 4), 256>>>();
    k_prep  <<<B_ * K_, 256>>>();
    k_maha  <<<dim3(CHUNKS_, B_), 128>>>(z);
    k_final <<<1, 1024>>>((float*)d_out);
}